// round 16
// baseline (speedup 1.0000x reference)
#include <cuda_runtime.h>
#include <cuda_bf16.h>
#include <math.h>
#include <stdint.h>

#define S_LEN 512
#define BATCH 64
#define HID 512
#define TAGS 50
#define K2 2500             // TAGS*TAGS
#define K2PH 2512           // padded row in halfs (5024 B, 16B mult)
#define START_TAG 48
#define END_TAG 49
#define M_TOT (S_LEN*BATCH) // 32768
#define NTILES 20           // ceil(2500/128)
#define NPAD (NTILES*128)   // 2560

// Scratch (no allocations allowed)
// E is stored PERMUTED: column n' = j*50 + i  <=>  E'[b,s,n'] = exp(score[s,b,i,j])
__device__ __align__(1024) unsigned short g_Eh[(size_t)M_TOT * K2PH];      // bf16 E', ~165 MB
__device__ __align__(1024) unsigned int g_Ah[(size_t)M_TOT * HID / 2];     // bf16 feats, tiled
__device__ __align__(1024) unsigned int g_Wh[(size_t)NPAD * HID / 2];      // bf16 W', tiled+permuted
__device__ int g_t64;   // target stored as int64 (vs int32)
__device__ int g_m32;   // mask stored as int32 (vs bool/byte)

// ===========================================================================
// PTX helpers
// ===========================================================================
__device__ __forceinline__ uint32_t smem_u32(const void* p) {
    uint32_t a;
    asm("{ .reg .u64 t; cvta.to.shared.u64 t, %1; cvt.u32.u64 %0, t; }" : "=r"(a) : "l"(p));
    return a;
}
#define MBAR_INIT(addr, cnt) \
    asm volatile("mbarrier.init.shared.b64 [%0], %1;" :: "r"(addr), "r"(cnt) : "memory")
#define MBAR_EXPECT_TX(addr, bytes) \
    asm volatile("mbarrier.arrive.expect_tx.shared.b64 _, [%0], %1;" :: "r"(addr), "r"(bytes) : "memory")
#define MBAR_WAIT(addr, par) do {                                              \
    uint32_t _m = (addr), _p = (par), _d;                                      \
    asm volatile("{\n\t.reg .pred p;\n\t"                                      \
        "mbarrier.try_wait.parity.acquire.cta.shared::cta.b64 p, [%1], %2;\n\t"\
        "selp.b32 %0, 1, 0, p;\n\t}" : "=r"(_d) : "r"(_m), "r"(_p) : "memory");\
    if (!_d) {                                                                 \
        asm volatile("{\n\t.reg .pred P1;\n\t"                                 \
            "W%=:\n\t"                                                         \
            "mbarrier.try_wait.parity.acquire.cta.shared::cta.b64 P1, [%0], %1, 0x989680;\n\t" \
            "@P1 bra.uni D%=;\n\t"                                             \
            "bra.uni W%=;\n\t"                                                 \
            "D%=:\n\t}" :: "r"(_m), "r"(_p) : "memory");                       \
    }                                                                          \
} while (0)
#define BULK_G2S(dst, src, bytes, bar) \
    asm volatile("cp.async.bulk.shared::cta.global.mbarrier::complete_tx::bytes [%0], [%1], %2, [%3];" \
        :: "r"(dst), "l"(src), "r"(bytes), "r"(bar) : "memory")

__device__ __forceinline__ uint32_t pack_bf16x2(float lo, float hi) {
    uint32_t r;
    asm("cvt.rn.bf16x2.f32 %0, %1, %2;" : "=r"(r) : "f"(hi), "f"(lo));
    return r;
}
__device__ __forceinline__ float bf2f(unsigned short u) {
    return __uint_as_float(((unsigned int)u) << 16);
}
// FFMA-only exp (rel err <= 4.2e-5)
__device__ __forceinline__ float fast_exp(float x) {
    float z = __fmul_rn(x, 1.44269504f);
    float t = __fadd_rn(z, 12582912.0f);
    float n = __fadd_rn(t, -12582912.0f);
    float f = __fadd_rn(z, -n);
    float p = 0.00961812910f;
    p = fmaf(p, f, 0.05550410866f);
    p = fmaf(p, f, 0.24022650696f);
    p = fmaf(p, f, 0.69314718056f);
    p = fmaf(p, f, 1.0f);
    return __int_as_float(__float_as_int(p) + (__float_as_int(t) << 23));
}
__device__ __forceinline__ void mma_bf16(float& d0, float& d1, float& d2, float& d3,
                                         uint32_t a0, uint32_t a1, uint32_t a2, uint32_t a3,
                                         uint32_t b0, uint32_t b1) {
    asm volatile(
        "mma.sync.aligned.m16n8k16.row.col.f32.bf16.bf16.f32 "
        "{%0,%1,%2,%3},{%4,%5,%6,%7},{%8,%9},{%0,%1,%2,%3};"
        : "+f"(d0), "+f"(d1), "+f"(d2), "+f"(d3)
        : "r"(a0), "r"(a1), "r"(a2), "r"(a3), "r"(b0), "r"(b1));
}

// ===========================================================================
// Kernel 0: zero output + detect input storage widths
// ===========================================================================
__global__ void init_kernel(float* out, const void* target, const void* mask) {
    if (threadIdx.x == 0) {
        out[0] = 0.0f;
        const unsigned int* tw = (const unsigned int*)target;
        unsigned int nz = 0;
#pragma unroll
        for (int q = 0; q < 64; q++) nz |= tw[2 * q + 1];
        g_t64 = (nz == 0) ? 1 : 0;
        const unsigned int* mw = (const unsigned int*)mask;
        unsigned int big = 0;
#pragma unroll
        for (int q = 0; q < 64; q++) big |= (mw[q] > 1u) ? 1u : 0u;
        g_m32 = big ? 0 : 1;
    }
}
__device__ __forceinline__ bool mask_at(const void* mask, int idx) {
    if (g_m32) return ((const int*)mask)[idx] != 0;
    return ((const unsigned char*)mask)[idx] != 0;
}

// ===========================================================================
// Kernel 0b: convert feats -> bf16 tiles; W -> bf16 PERMUTED tiles.
// tile = 128 rows x 32 k-halfs = 8 KB contiguous ([rowtile][chunk][row][32h]).
// W' row n' = j*50+i reads W row i*50+j  (n' >= 2500 -> zeros).
// ===========================================================================
__global__ __launch_bounds__(256) void cvt_kernel(
    const float* __restrict__ A, const float* __restrict__ W)
{
    const int stride = gridDim.x * blockDim.x;
    for (int id = blockIdx.x * blockDim.x + threadIdx.x; id < M_TOT * 256; id += stride) {
        int m = id >> 8, kp = id & 255;
        float2 v = ((const float2*)A)[id];
        int tile = (m >> 7) * 16 + (kp >> 4);
        g_Ah[tile * 2048 + (m & 127) * 16 + (kp & 15)] = pack_bf16x2(v.x, v.y);
    }
    for (int id = blockIdx.x * blockDim.x + threadIdx.x; id < NPAD * 256; id += stride) {
        int np = id >> 8, kp = id & 255;
        unsigned int o = 0;
        if (np < K2) {
            int orig = (np % TAGS) * TAGS + np / TAGS;   // W row i*50+j for n'=j*50+i
            float2 v = ((const float2*)W)[orig * 256 + kp];
            o = pack_bf16x2(v.x, v.y);
        }
        int tile = (np >> 7) * 16 + (kp >> 4);
        g_Wh[tile * 2048 + (np & 127) * 16 + (kp & 15)] = o;
    }
}

// ===========================================================================
// Kernel 1: bf16 mma.sync GEMM + fast-exp epilogue -> g_Eh (bf16, permuted cols)
// BM=BN=128. STAGES OF BK=64: each stage = 16 KB A + 16 KB B (2 contiguous
// 8 KB chunks each), filled by 2 cp.async.bulk. 3-stage ring, 8 iterations,
// one __syncthreads per iteration (half of R13's barrier count).
// ===========================================================================
#define NITER 8
#define CHUNKB 8192
#define STAGE_A 16384                   // 2 A-chunks
#define STAGE_SZ 32768                  // A + B per stage
#define NSTAGE 3
#define RPH 136                         // staging row stride in halfs (272 B)
#define STAGEBYTES (128 * RPH * 2)      // 34816 (overlays the stage buffers)
#define BIASOFF (NSTAGE * STAGE_SZ)     // 98304
#define GEMM_SMEM (BIASOFF + 512 + 64)

__global__ __launch_bounds__(256, 2) void gemm_tc_kernel(const float* __restrict__ bias)
{
    extern __shared__ char smem[];
    const uint32_t sbase = smem_u32(smem);
    const int tid = threadIdx.x;
    const int nt0 = blockIdx.x;        // n tile
    const int mt0 = blockIdx.y;        // m tile
    const int n0 = nt0 * 128;
    const int m0 = mt0 * 128;
    float* sbias = (float*)(smem + BIASOFF);
    const uint32_t mb = sbase + BIASOFF + 512;

    if (tid < 128) {
        int np = n0 + tid;
        sbias[tid] = (np < K2) ? bias[(np % TAGS) * TAGS + np / TAGS] : 0.0f;
    }
    if (tid == 0) {
#pragma unroll
        for (int q = 0; q < NSTAGE; q++) MBAR_INIT(mb + 8 * q, 1);
    }
    __syncthreads();

    const char* gA = (const char*)g_Ah + (size_t)mt0 * 16 * CHUNKB;
    const char* gW = (const char*)g_Wh + (size_t)nt0 * 16 * CHUNKB;

    auto issue = [&](int c) {
        const int st = c % NSTAGE;
        const uint32_t bar = mb + 8 * st;
        MBAR_EXPECT_TX(bar, STAGE_SZ);
        BULK_G2S(sbase + st * STAGE_SZ,           gA + (size_t)c * STAGE_A, STAGE_A, bar);
        BULK_G2S(sbase + st * STAGE_SZ + STAGE_A, gW + (size_t)c * STAGE_A, STAGE_A, bar);
    };
    if (tid == 0) { issue(0); issue(1); }

    const int w = tid >> 5;
    const int lane = tid & 31;
    const int g = lane >> 2;       // row within 8
    const int t = lane & 3;        // 16B segment
    const int wm = w >> 2;         // 0..1 -> m offset wm*64
    const int wn = w & 3;          // 0..3 -> n offset wn*32

    float acc[4][4][4];
#pragma unroll
    for (int i = 0; i < 4; i++)
#pragma unroll
        for (int j = 0; j < 4; j++)
#pragma unroll
            for (int q = 0; q < 4; q++) acc[i][j][q] = 0.0f;

    for (int c = 0; c < NITER; c++) {
        if (tid == 0 && c + 2 < NITER) issue(c + 2);
        MBAR_WAIT(mb + 8 * (c % NSTAGE), ((c / NSTAGE) & 1));

        const char* stage = smem + (c % NSTAGE) * STAGE_SZ;
#pragma unroll
        for (int h = 0; h < 2; h++) {
            const char* sA = stage + h * CHUNKB;
            const char* sB = stage + STAGE_A + h * CHUNKB;

            uint4 bfr[4];
#pragma unroll
            for (int nt = 0; nt < 4; nt++)
                bfr[nt] = *(const uint4*)(sB + (wn * 32 + nt * 8 + g) * 64 + t * 16);
#pragma unroll
            for (int i = 0; i < 4; i++) {
                const int ra = wm * 64 + i * 16 + g;
                uint4 a0 = *(const uint4*)(sA + ra * 64 + t * 16);
                uint4 a1 = *(const uint4*)(sA + (ra + 8) * 64 + t * 16);
#pragma unroll
                for (int nt = 0; nt < 4; nt++) {
                    mma_bf16(acc[i][nt][0], acc[i][nt][1], acc[i][nt][2], acc[i][nt][3],
                             a0.x, a1.x, a0.y, a1.y, bfr[nt].x, bfr[nt].y);
                    mma_bf16(acc[i][nt][0], acc[i][nt][1], acc[i][nt][2], acc[i][nt][3],
                             a0.z, a1.z, a0.w, a1.w, bfr[nt].z, bfr[nt].w);
                }
            }
        }
        __syncthreads();   // all warps done with this stage before its refill
    }

    // ---- epilogue: E' = bf16(fast_exp(D + bias')) into padded SMEM stage ----
    unsigned short* stg = (unsigned short*)smem;
#pragma unroll
    for (int i = 0; i < 4; i++) {
        const int rloc = wm * 64 + i * 16 + g;
#pragma unroll
        for (int nt = 0; nt < 4; nt++) {
            const int cloc = wn * 32 + nt * 8 + 2 * t;
            const float bz0 = sbias[cloc], bz1 = sbias[cloc + 1];
            unsigned int u0 = pack_bf16x2(fast_exp(acc[i][nt][0] + bz0),
                                          fast_exp(acc[i][nt][1] + bz1));
            unsigned int u1 = pack_bf16x2(fast_exp(acc[i][nt][2] + bz0),
                                          fast_exp(acc[i][nt][3] + bz1));
            *(unsigned int*)&stg[rloc * RPH + cloc] = u0;
            *(unsigned int*)&stg[(rloc + 8) * RPH + cloc] = u1;
        }
    }
    __syncthreads();

    // ---- coalesced store-out ----
#pragma unroll
    for (int it = 0; it < 8; it++) {
        int u = tid + it * 256;
        int r = u >> 4;
        int sg = u & 15;
        int colh = sg * 8;
        if (n0 + colh + 8 <= K2PH) {
            uint4 v = *(const uint4*)&stg[r * RPH + colh];
            *(uint4*)&g_Eh[(size_t)(m0 + r) * K2PH + n0 + colh] = v;
        }
    }
}

// ===========================================================================
// Kernel 2: target energy. Block-reduces and atomicAdds -tg/B directly into
// out (order-independent with scan's +pEnd/B contribution).
// ===========================================================================
__global__ __launch_bounds__(256) void tg_kernel(
    const float* __restrict__ feats, const float* __restrict__ W,
    const float* __restrict__ bias, const void* __restrict__ target,
    const void* __restrict__ mask, float* __restrict__ out)
{
    __shared__ float wsum[8];
    const int warp = (blockIdx.x * blockDim.x + threadIdx.x) >> 5;
    const int wid = threadIdx.x >> 5;
    const int lane = threadIdx.x & 31;

    float val = 0.0f;
    if (warp < M_TOT) {
        long long t;
        if (g_t64) t = ((const long long*)target)[warp];
        else       t = (long long)((const int*)target)[warp];

        const float4* a  = (const float4*)(feats + (size_t)warp * HID);
        const float4* w4 = (const float4*)(W + (size_t)t * HID);
        float s = 0.0f;
#pragma unroll
        for (int u = 0; u < 4; u++) {
            float4 av = a[lane + u * 32];
            float4 wv = w4[lane + u * 32];
            s += av.x * wv.x + av.y * wv.y + av.z * wv.z + av.w * wv.w;
        }
#pragma unroll
        for (int off = 16; off; off >>= 1) s += __shfl_xor_sync(0xffffffffu, s, off);
        val = mask_at(mask, warp) ? (s + bias[t]) : 0.0f;
    }
    if (lane == 0) wsum[wid] = val;
    __syncthreads();
    if (threadIdx.x == 0) {
        float tot = 0.0f;
#pragma unroll
        for (int q = 0; q < 8; q++) tot += wsum[q];
        atomicAdd(out, -tot / (float)BATCH);
    }
}

// ===========================================================================
// Kernel 3: sequential forward scan, one block (64 thr) per batch element.
// Permuted E': thread j reads halfs [j*50 .. j*50+49] contiguously (25 LDS.U32).
// Mask preloaded to smem. pe in registers (13 broadcast LDS.128 over mbar wait).
// ===========================================================================
#define NSTG 8
#define STAGEB (K2PH * 2)    // 5024 bytes per stage

__global__ __launch_bounds__(64) void scan_kernel(
    const void* __restrict__ mask, float* __restrict__ out)
{
    __shared__ __align__(16) unsigned short Es[NSTG][K2PH];
    __shared__ __align__(8) unsigned long long mbar[NSTG];
    __shared__ __align__(16) float pe[56];
    __shared__ unsigned char smask[S_LEN];
    __shared__ float s_q0;

    const int b = blockIdx.x;
    const int tid = threadIdx.x;
    const uint32_t mb = smem_u32(mbar);
    const uint32_t esb = smem_u32(Es);

    if (tid == 0) {
#pragma unroll
        for (int q = 0; q < NSTG; q++) MBAR_INIT(mb + 8 * q, 1);
    }
    // preload mask column b into smem (one-time)
    for (int s = tid; s < S_LEN; s += 64)
        smask[s] = mask_at(mask, s * BATCH + b) ? 1 : 0;

    // init: pe = p0 / p0[0];  p0[j] = E'[0,b, j*50+START_TAG]
    float e0 = 0.0f;
    if (tid < TAGS)
        e0 = bf2f(g_Eh[(size_t)b * K2PH + tid * TAGS + START_TAG]);
    if (tid == 0) s_q0 = e0;
    if (tid >= TAGS && tid < 56) pe[tid] = 0.0f;   // pad (never used in dot)
    __syncthreads();
    float logoff = 0.0f;
    if (tid == 0) logoff = __logf(s_q0);
    if (tid < TAGS) pe[tid] = e0 / s_q0;

    // prefetch stages for s=1..7
    if (tid == 0) {
#pragma unroll
        for (int t = 1; t <= NSTG - 1; t++) {
            int st = (t - 1) & (NSTG - 1);
            MBAR_EXPECT_TX(mb + 8 * st, STAGEB);
            BULK_G2S(esb + st * STAGEB,
                     (const char*)g_Eh + (size_t)(t * BATCH + b) * STAGEB,
                     STAGEB, mb + 8 * st);
        }
    }
    __syncthreads();

    for (int s = 1; s < S_LEN; s++) {
        const int st = (s - 1) & (NSTG - 1);
        if (tid == 0 && s + NSTG - 1 < S_LEN) {
            int ps = (s + NSTG - 2) & (NSTG - 1);
            MBAR_EXPECT_TX(mb + 8 * ps, STAGEB);
            BULK_G2S(esb + ps * STAGEB,
                     (const char*)g_Eh + (size_t)((s + NSTG - 1) * BATCH + b) * STAGEB,
                     STAGEB, mb + 8 * ps);
        }

        // pe -> registers (broadcast LDS.128, overlaps the mbar wait below)
        float pr[52];
#pragma unroll
        for (int u = 0; u < 13; u++) {
            float4 v = *(const float4*)&pe[u * 4];
            pr[u * 4 + 0] = v.x; pr[u * 4 + 1] = v.y;
            pr[u * 4 + 2] = v.z; pr[u * 4 + 3] = v.w;
        }
        const bool m = smask[s] != 0;
        MBAR_WAIT(mb + 8 * st, ((s - 1) >> 3) & 1);

        float q = 0.0f;
        if (tid < TAGS) {
            const unsigned int* E =
                (const unsigned int*)((const char*)Es[st] + tid * (TAGS * 2));
            float a0 = 0.0f, a1 = 0.0f, a2 = 0.0f, a3 = 0.0f;
#pragma unroll
            for (int u = 0; u < 24; u += 4) {
                unsigned int e0u = E[u], e1u = E[u + 1], e2u = E[u + 2], e3u = E[u + 3];
                a0 = fmaf(__uint_as_float(e0u << 16), pr[2 * u + 0], a0);
                a1 = fmaf(__uint_as_float(e0u & 0xFFFF0000u), pr[2 * u + 1], a1);
                a2 = fmaf(__uint_as_float(e1u << 16), pr[2 * u + 2], a2);
                a3 = fmaf(__uint_as_float(e1u & 0xFFFF0000u), pr[2 * u + 3], a3);
                a0 = fmaf(__uint_as_float(e2u << 16), pr[2 * u + 4], a0);
                a1 = fmaf(__uint_as_float(e2u & 0xFFFF0000u), pr[2 * u + 5], a1);
                a2 = fmaf(__uint_as_float(e3u << 16), pr[2 * u + 6], a2);
                a3 = fmaf(__uint_as_float(e3u & 0xFFFF0000u), pr[2 * u + 7], a3);
            }
            unsigned int eL = E[24];
            a0 = fmaf(__uint_as_float(eL << 16), pr[48], a0);
            a1 = fmaf(__uint_as_float(eL & 0xFFFF0000u), pr[49], a1);
            q = (a0 + a1) + (a2 + a3);
            if (tid == 0) s_q0 = q;
        }
        __syncthreads();            // E reads done (stage reusable) + s_q0 visible
        if (m) {
            if (tid < TAGS) pe[tid] = __fdividef(q, s_q0);
            if (tid == 0) logoff += __logf(s_q0);
        }
        __syncthreads();            // pe writes done before next step's pr load
    }

    // epilogue: loss contribution = (log(pe[END]) + logoff) / B
    if (tid == 0) {
        float pEnd = __logf(pe[END_TAG]) + logoff;
        atomicAdd(out, pEnd / (float)BATCH);
    }
}

// ===========================================================================
extern "C" void kernel_launch(void* const* d_in, const int* in_sizes, int n_in,
                              void* d_out, int out_size)
{
    const float* feats  = (const float*)d_in[0];
    const float* W      = (const float*)d_in[1];
    const float* bias   = (const float*)d_in[2];
    const void*  target = d_in[3];
    const void*  mask   = (const void*)d_in[4];
    float* out = (float*)d_out;

    cudaFuncSetAttribute(gemm_tc_kernel,
                         cudaFuncAttributeMaxDynamicSharedMemorySize, GEMM_SMEM);

    init_kernel<<<1, 32>>>(out, target, mask);
    cvt_kernel<<<1184, 256>>>(feats, W);

    dim3 ggrid(NTILES, M_TOT / 128);   // 20 x 256
    gemm_tc_kernel<<<ggrid, 256, GEMM_SMEM>>>(bias);

    // scan is now the 4th launch -> ncu capture slot lands on it.
    scan_kernel<<<BATCH, 64>>>(mask, out);

    // tg contributes -tg/B directly to out; independent of scan ordering.
    tg_kernel<<<M_TOT / 8, 256>>>(feats, W, bias, target, mask, out);
}

// round 17
// speedup vs baseline: 1.4107x; 1.4107x over previous
#include <cuda_runtime.h>
#include <cuda_bf16.h>
#include <math.h>
#include <stdint.h>

#define S_LEN 512
#define BATCH 64
#define HID 512
#define TAGS 50
#define K2 2500             // TAGS*TAGS
#define K2PH 2512           // padded row in halfs (5024 B, 16B mult)
#define START_TAG 48
#define END_TAG 49
#define M_TOT (S_LEN*BATCH) // 32768
#define NTILES 20           // ceil(2500/128)
#define NPAD (NTILES*128)   // 2560

// Scratch (no allocations allowed)
// E is stored PERMUTED: column n' = j*50 + i  <=>  E'[b,s,n'] = exp(score[s,b,i,j])
__device__ __align__(1024) unsigned short g_Eh[(size_t)M_TOT * K2PH];      // bf16 E', ~165 MB
__device__ __align__(1024) unsigned int g_Ah[(size_t)M_TOT * HID / 2];     // bf16 feats, tiled
__device__ __align__(1024) unsigned int g_Wh[(size_t)NPAD * HID / 2];      // bf16 W', tiled+permuted
__device__ int g_t64;   // target stored as int64 (vs int32)
__device__ int g_m32;   // mask stored as int32 (vs bool/byte)

// ===========================================================================
// PTX helpers
// ===========================================================================
__device__ __forceinline__ uint32_t smem_u32(const void* p) {
    uint32_t a;
    asm("{ .reg .u64 t; cvta.to.shared.u64 t, %1; cvt.u32.u64 %0, t; }" : "=r"(a) : "l"(p));
    return a;
}
#define MBAR_INIT(addr, cnt) \
    asm volatile("mbarrier.init.shared.b64 [%0], %1;" :: "r"(addr), "r"(cnt) : "memory")
#define MBAR_EXPECT_TX(addr, bytes) \
    asm volatile("mbarrier.arrive.expect_tx.shared.b64 _, [%0], %1;" :: "r"(addr), "r"(bytes) : "memory")
#define MBAR_WAIT(addr, par) do {                                              \
    uint32_t _m = (addr), _p = (par), _d;                                      \
    asm volatile("{\n\t.reg .pred p;\n\t"                                      \
        "mbarrier.try_wait.parity.acquire.cta.shared::cta.b64 p, [%1], %2;\n\t"\
        "selp.b32 %0, 1, 0, p;\n\t}" : "=r"(_d) : "r"(_m), "r"(_p) : "memory");\
    if (!_d) {                                                                 \
        asm volatile("{\n\t.reg .pred P1;\n\t"                                 \
            "W%=:\n\t"                                                         \
            "mbarrier.try_wait.parity.acquire.cta.shared::cta.b64 P1, [%0], %1, 0x989680;\n\t" \
            "@P1 bra.uni D%=;\n\t"                                             \
            "bra.uni W%=;\n\t"                                                 \
            "D%=:\n\t}" :: "r"(_m), "r"(_p) : "memory");                       \
    }                                                                          \
} while (0)
#define BULK_G2S(dst, src, bytes, bar) \
    asm volatile("cp.async.bulk.shared::cta.global.mbarrier::complete_tx::bytes [%0], [%1], %2, [%3];" \
        :: "r"(dst), "l"(src), "r"(bytes), "r"(bar) : "memory")

__device__ __forceinline__ uint32_t pack_bf16x2(float lo, float hi) {
    uint32_t r;
    asm("cvt.rn.bf16x2.f32 %0, %1, %2;" : "=r"(r) : "f"(hi), "f"(lo));
    return r;
}
__device__ __forceinline__ float bf2f(unsigned short u) {
    return __uint_as_float(((unsigned int)u) << 16);
}
// FFMA-only exp (rel err <= 4.2e-5)
__device__ __forceinline__ float fast_exp(float x) {
    float z = __fmul_rn(x, 1.44269504f);
    float t = __fadd_rn(z, 12582912.0f);
    float n = __fadd_rn(t, -12582912.0f);
    float f = __fadd_rn(z, -n);
    float p = 0.00961812910f;
    p = fmaf(p, f, 0.05550410866f);
    p = fmaf(p, f, 0.24022650696f);
    p = fmaf(p, f, 0.69314718056f);
    p = fmaf(p, f, 1.0f);
    return __int_as_float(__float_as_int(p) + (__float_as_int(t) << 23));
}
__device__ __forceinline__ void mma_bf16(float& d0, float& d1, float& d2, float& d3,
                                         uint32_t a0, uint32_t a1, uint32_t a2, uint32_t a3,
                                         uint32_t b0, uint32_t b1) {
    asm volatile(
        "mma.sync.aligned.m16n8k16.row.col.f32.bf16.bf16.f32 "
        "{%0,%1,%2,%3},{%4,%5,%6,%7},{%8,%9},{%0,%1,%2,%3};"
        : "+f"(d0), "+f"(d1), "+f"(d2), "+f"(d3)
        : "r"(a0), "r"(a1), "r"(a2), "r"(a3), "r"(b0), "r"(b1));
}

// ===========================================================================
// Kernel 0: zero output + detect input storage widths
// ===========================================================================
__global__ void init_kernel(float* out, const void* target, const void* mask) {
    if (threadIdx.x == 0) {
        out[0] = 0.0f;
        const unsigned int* tw = (const unsigned int*)target;
        unsigned int nz = 0;
#pragma unroll
        for (int q = 0; q < 64; q++) nz |= tw[2 * q + 1];
        g_t64 = (nz == 0) ? 1 : 0;
        const unsigned int* mw = (const unsigned int*)mask;
        unsigned int big = 0;
#pragma unroll
        for (int q = 0; q < 64; q++) big |= (mw[q] > 1u) ? 1u : 0u;
        g_m32 = big ? 0 : 1;
    }
}
__device__ __forceinline__ bool mask_at(const void* mask, int idx) {
    if (g_m32) return ((const int*)mask)[idx] != 0;
    return ((const unsigned char*)mask)[idx] != 0;
}

// ===========================================================================
// Kernel 0b: convert feats -> bf16 tiles; W -> bf16 PERMUTED tiles.
// tile = 128 rows x 32 k-halfs = 8 KB contiguous ([rowtile][chunk][row][32h]).
// W' row n' = j*50+i reads W row i*50+j  (n' >= 2500 -> zeros).
// ===========================================================================
__global__ __launch_bounds__(256) void cvt_kernel(
    const float* __restrict__ A, const float* __restrict__ W)
{
    const int stride = gridDim.x * blockDim.x;
    for (int id = blockIdx.x * blockDim.x + threadIdx.x; id < M_TOT * 256; id += stride) {
        int m = id >> 8, kp = id & 255;
        float2 v = ((const float2*)A)[id];
        int tile = (m >> 7) * 16 + (kp >> 4);
        g_Ah[tile * 2048 + (m & 127) * 16 + (kp & 15)] = pack_bf16x2(v.x, v.y);
    }
    for (int id = blockIdx.x * blockDim.x + threadIdx.x; id < NPAD * 256; id += stride) {
        int np = id >> 8, kp = id & 255;
        unsigned int o = 0;
        if (np < K2) {
            int orig = (np % TAGS) * TAGS + np / TAGS;   // W row i*50+j for n'=j*50+i
            float2 v = ((const float2*)W)[orig * 256 + kp];
            o = pack_bf16x2(v.x, v.y);
        }
        int tile = (np >> 7) * 16 + (kp >> 4);
        g_Wh[tile * 2048 + (np & 127) * 16 + (kp & 15)] = o;
    }
}

// ===========================================================================
// Kernel 1: bf16 mma.sync GEMM + fast-exp epilogue (R13-passing version:
// BM=BN=128, k chunks of 32, 3-stage 16 KB ring — profiled 256 us).
// ===========================================================================
#define NCHUNK 16
#define TILEB 8192
#define BUFSZ (2*TILEB)                 // A+B per stage (16 KB)
#define NSTAGE 3
#define RPH 136                         // staging row stride in halfs (272 B)
#define STAGEBYTES (128 * RPH * 2)      // 34816 (overlays the stage buffers)
#define BIASOFF (NSTAGE * BUFSZ)        // 49152
#define GEMM_SMEM (BIASOFF + 512 + 64)

__global__ __launch_bounds__(256, 2) void gemm_tc_kernel(const float* __restrict__ bias)
{
    extern __shared__ char smem[];
    const uint32_t sbase = smem_u32(smem);
    const int tid = threadIdx.x;
    const int nt0 = blockIdx.x;        // n tile
    const int mt0 = blockIdx.y;        // m tile
    const int n0 = nt0 * 128;
    const int m0 = mt0 * 128;
    float* sbias = (float*)(smem + BIASOFF);
    const uint32_t mb = sbase + BIASOFF + 512;

    if (tid < 128) {
        int np = n0 + tid;
        sbias[tid] = (np < K2) ? bias[(np % TAGS) * TAGS + np / TAGS] : 0.0f;
    }
    if (tid == 0) {
#pragma unroll
        for (int q = 0; q < NSTAGE; q++) MBAR_INIT(mb + 8 * q, 1);
    }
    __syncthreads();

    const char* gA = (const char*)g_Ah + (size_t)mt0 * 16 * TILEB;
    const char* gW = (const char*)g_Wh + (size_t)nt0 * 16 * TILEB;

    auto issue = [&](int c) {
        const int st = c % NSTAGE;
        const uint32_t bar = mb + 8 * st;
        MBAR_EXPECT_TX(bar, 2 * TILEB);
        BULK_G2S(sbase + st * BUFSZ,         gA + (size_t)c * TILEB, TILEB, bar);
        BULK_G2S(sbase + st * BUFSZ + TILEB, gW + (size_t)c * TILEB, TILEB, bar);
    };
    if (tid == 0) { issue(0); issue(1); }

    const int w = tid >> 5;
    const int lane = tid & 31;
    const int g = lane >> 2;       // row within 8
    const int t = lane & 3;        // 16B segment
    const int wm = w >> 2;         // 0..1 -> m offset wm*64
    const int wn = w & 3;          // 0..3 -> n offset wn*32

    float acc[4][4][4];
#pragma unroll
    for (int i = 0; i < 4; i++)
#pragma unroll
        for (int j = 0; j < 4; j++)
#pragma unroll
            for (int q = 0; q < 4; q++) acc[i][j][q] = 0.0f;

    for (int c = 0; c < NCHUNK; c++) {
        if (tid == 0 && c + 2 < NCHUNK) issue(c + 2);
        MBAR_WAIT(mb + 8 * (c % NSTAGE), ((c / NSTAGE) & 1));

        const char* sA = smem + (c % NSTAGE) * BUFSZ;
        const char* sB = sA + TILEB;

        uint4 bfr[4];
#pragma unroll
        for (int nt = 0; nt < 4; nt++)
            bfr[nt] = *(const uint4*)(sB + (wn * 32 + nt * 8 + g) * 64 + t * 16);
#pragma unroll
        for (int i = 0; i < 4; i++) {
            const int ra = wm * 64 + i * 16 + g;
            uint4 a0 = *(const uint4*)(sA + ra * 64 + t * 16);
            uint4 a1 = *(const uint4*)(sA + (ra + 8) * 64 + t * 16);
#pragma unroll
            for (int nt = 0; nt < 4; nt++) {
                mma_bf16(acc[i][nt][0], acc[i][nt][1], acc[i][nt][2], acc[i][nt][3],
                         a0.x, a1.x, a0.y, a1.y, bfr[nt].x, bfr[nt].y);
                mma_bf16(acc[i][nt][0], acc[i][nt][1], acc[i][nt][2], acc[i][nt][3],
                         a0.z, a1.z, a0.w, a1.w, bfr[nt].z, bfr[nt].w);
            }
        }
        __syncthreads();
    }

    // ---- epilogue: E' = bf16(fast_exp(D + bias')) into padded SMEM stage ----
    unsigned short* stg = (unsigned short*)smem;
#pragma unroll
    for (int i = 0; i < 4; i++) {
        const int rloc = wm * 64 + i * 16 + g;
#pragma unroll
        for (int nt = 0; nt < 4; nt++) {
            const int cloc = wn * 32 + nt * 8 + 2 * t;
            const float bz0 = sbias[cloc], bz1 = sbias[cloc + 1];
            unsigned int u0 = pack_bf16x2(fast_exp(acc[i][nt][0] + bz0),
                                          fast_exp(acc[i][nt][1] + bz1));
            unsigned int u1 = pack_bf16x2(fast_exp(acc[i][nt][2] + bz0),
                                          fast_exp(acc[i][nt][3] + bz1));
            *(unsigned int*)&stg[rloc * RPH + cloc] = u0;
            *(unsigned int*)&stg[(rloc + 8) * RPH + cloc] = u1;
        }
    }
    __syncthreads();

    // ---- coalesced store-out ----
#pragma unroll
    for (int it = 0; it < 8; it++) {
        int u = tid + it * 256;
        int r = u >> 4;
        int sg = u & 15;
        int colh = sg * 8;
        if (n0 + colh + 8 <= K2PH) {
            uint4 v = *(const uint4*)&stg[r * RPH + colh];
            *(uint4*)&g_Eh[(size_t)(m0 + r) * K2PH + n0 + colh] = v;
        }
    }
}

// ===========================================================================
// Kernel 2: target energy -> atomicAdd(-tg/B) into out (order-independent)
// ===========================================================================
__global__ __launch_bounds__(256) void tg_kernel(
    const float* __restrict__ feats, const float* __restrict__ W,
    const float* __restrict__ bias, const void* __restrict__ target,
    const void* __restrict__ mask, float* __restrict__ out)
{
    __shared__ float wsum[8];
    const int warp = (blockIdx.x * blockDim.x + threadIdx.x) >> 5;
    const int wid = threadIdx.x >> 5;
    const int lane = threadIdx.x & 31;

    float val = 0.0f;
    if (warp < M_TOT) {
        long long t;
        if (g_t64) t = ((const long long*)target)[warp];
        else       t = (long long)((const int*)target)[warp];

        const float4* a  = (const float4*)(feats + (size_t)warp * HID);
        const float4* w4 = (const float4*)(W + (size_t)t * HID);
        float s = 0.0f;
#pragma unroll
        for (int u = 0; u < 4; u++) {
            float4 av = a[lane + u * 32];
            float4 wv = w4[lane + u * 32];
            s += av.x * wv.x + av.y * wv.y + av.z * wv.z + av.w * wv.w;
        }
#pragma unroll
        for (int off = 16; off; off >>= 1) s += __shfl_xor_sync(0xffffffffu, s, off);
        val = mask_at(mask, warp) ? (s + bias[t]) : 0.0f;
    }
    if (lane == 0) wsum[wid] = val;
    __syncthreads();
    if (threadIdx.x == 0) {
        float tot = 0.0f;
#pragma unroll
        for (int q = 0; q < 8; q++) tot += wsum[q];
        atomicAdd(out, -tot / (float)BATCH);
    }
}

// ===========================================================================
// Kernel 3: forward scan, one block of 128 THREADS per batch element.
// TWO threads per tag j (pair tid=2j, 2j+1): h=0 covers E-words 0..12
// (elements 0..25), h=1 words 13..24 (elements 26..49); partials combined
// with shfl_xor(q,1). Uses 4 SMSPs, halves per-thread chain length.
// ===========================================================================
#define NSTG 8
#define STAGEB (K2PH * 2)    // 5024 bytes per stage

__global__ __launch_bounds__(128) void scan_kernel(
    const void* __restrict__ mask, float* __restrict__ out)
{
    __shared__ __align__(16) unsigned short Es[NSTG][K2PH];
    __shared__ __align__(8) unsigned long long mbar[NSTG];
    __shared__ __align__(16) float pe[56];
    __shared__ unsigned char smask[S_LEN];
    __shared__ float s_q0;

    const int b = blockIdx.x;
    const int tid = threadIdx.x;
    const int j = tid >> 1;        // tag index 0..63
    const int h = tid & 1;         // half 0/1
    const uint32_t mb = smem_u32(mbar);
    const uint32_t esb = smem_u32(Es);

    if (tid == 0) {
#pragma unroll
        for (int q = 0; q < NSTG; q++) MBAR_INIT(mb + 8 * q, 1);
    }
    for (int s = tid; s < S_LEN; s += 128)
        smask[s] = mask_at(mask, s * BATCH + b) ? 1 : 0;

    // init: pe = p0 / p0[0];  p0[jj] = E'[0,b, jj*50+START_TAG]
    float e0 = 0.0f;
    if (tid < TAGS)
        e0 = bf2f(g_Eh[(size_t)b * K2PH + tid * TAGS + START_TAG]);
    if (tid == 0) s_q0 = e0;
    if (tid >= TAGS && tid < 56) pe[tid] = 0.0f;
    __syncthreads();
    float logoff = 0.0f;
    if (tid == 0) logoff = __logf(s_q0);
    if (tid < TAGS) pe[tid] = e0 / s_q0;

    if (tid == 0) {
#pragma unroll
        for (int t = 1; t <= NSTG - 1; t++) {
            int st = (t - 1) & (NSTG - 1);
            MBAR_EXPECT_TX(mb + 8 * st, STAGEB);
            BULK_G2S(esb + st * STAGEB,
                     (const char*)g_Eh + (size_t)(t * BATCH + b) * STAGEB,
                     STAGEB, mb + 8 * st);
        }
    }
    __syncthreads();

    for (int s = 1; s < S_LEN; s++) {
        const int st = (s - 1) & (NSTG - 1);
        if (tid == 0 && s + NSTG - 1 < S_LEN) {
            int ps = (s + NSTG - 2) & (NSTG - 1);
            MBAR_EXPECT_TX(mb + 8 * ps, STAGEB);
            BULK_G2S(esb + ps * STAGEB,
                     (const char*)g_Eh + (size_t)((s + NSTG - 1) * BATCH + b) * STAGEB,
                     STAGEB, mb + 8 * ps);
        }

        // load my half of pe into registers (overlaps mbar wait)
        float pr[26];
        if (h == 0) {
#pragma unroll
            for (int u = 0; u < 6; u++) {
                float4 v = *(const float4*)&pe[u * 4];
                pr[u * 4 + 0] = v.x; pr[u * 4 + 1] = v.y;
                pr[u * 4 + 2] = v.z; pr[u * 4 + 3] = v.w;
            }
            float2 v = *(const float2*)&pe[24];
            pr[24] = v.x; pr[25] = v.y;
        } else {
            float2 v0 = *(const float2*)&pe[26];
            pr[0] = v0.x; pr[1] = v0.y;
#pragma unroll
            for (int u = 0; u < 5; u++) {
                float4 v = *(const float4*)&pe[28 + u * 4];
                pr[2 + u * 4 + 0] = v.x; pr[2 + u * 4 + 1] = v.y;
                pr[2 + u * 4 + 2] = v.z; pr[2 + u * 4 + 3] = v.w;
            }
            float2 v1 = *(const float2*)&pe[48];
            pr[22] = v1.x; pr[23] = v1.y;
        }
        const bool m = smask[s] != 0;
        MBAR_WAIT(mb + 8 * st, ((s - 1) >> 3) & 1);

        float q = 0.0f;
        if (j < TAGS) {
            const unsigned int* E =
                (const unsigned int*)Es[st] + j * 25 + h * 13;
            float a0 = 0.0f, a1 = 0.0f, a2 = 0.0f, a3 = 0.0f;
#pragma unroll
            for (int u = 0; u < 12; u += 4) {
                unsigned int e0u = E[u], e1u = E[u + 1], e2u = E[u + 2], e3u = E[u + 3];
                a0 = fmaf(__uint_as_float(e0u << 16), pr[2 * u + 0], a0);
                a1 = fmaf(__uint_as_float(e0u & 0xFFFF0000u), pr[2 * u + 1], a1);
                a2 = fmaf(__uint_as_float(e1u << 16), pr[2 * u + 2], a2);
                a3 = fmaf(__uint_as_float(e1u & 0xFFFF0000u), pr[2 * u + 3], a3);
                a0 = fmaf(__uint_as_float(e2u << 16), pr[2 * u + 4], a0);
                a1 = fmaf(__uint_as_float(e2u & 0xFFFF0000u), pr[2 * u + 5], a1);
                a2 = fmaf(__uint_as_float(e3u << 16), pr[2 * u + 6], a2);
                a3 = fmaf(__uint_as_float(e3u & 0xFFFF0000u), pr[2 * u + 7], a3);
            }
            if (h == 0) {                 // 13th word (elements 24,25)
                unsigned int eL = E[12];
                a0 = fmaf(__uint_as_float(eL << 16), pr[24], a0);
                a1 = fmaf(__uint_as_float(eL & 0xFFFF0000u), pr[25], a1);
            }
            q = (a0 + a1) + (a2 + a3);
        }
        q += __shfl_xor_sync(0xffffffffu, q, 1);   // combine halves
        if (tid == 0) s_q0 = q;
        __syncthreads();            // E reads done (stage reusable) + s_q0 visible
        if (m) {
            if (j < TAGS && h == 0) pe[j] = __fdividef(q, s_q0);
            if (tid == 0) logoff += __logf(s_q0);
        }
        __syncthreads();            // pe writes done before next step's pr load
    }

    // epilogue: loss contribution = (log(pe[END]) + logoff) / B
    if (tid == 0) {
        float pEnd = __logf(pe[END_TAG]) + logoff;
        atomicAdd(out, pEnd / (float)BATCH);
    }
}

// ===========================================================================
extern "C" void kernel_launch(void* const* d_in, const int* in_sizes, int n_in,
                              void* d_out, int out_size)
{
    const float* feats  = (const float*)d_in[0];
    const float* W      = (const float*)d_in[1];
    const float* bias   = (const float*)d_in[2];
    const void*  target = d_in[3];
    const void*  mask   = (const void*)d_in[4];
    float* out = (float*)d_out;

    cudaFuncSetAttribute(gemm_tc_kernel,
                         cudaFuncAttributeMaxDynamicSharedMemorySize, GEMM_SMEM);

    init_kernel<<<1, 32>>>(out, target, mask);
    cvt_kernel<<<1184, 256>>>(feats, W);

    dim3 ggrid(NTILES, M_TOT / 128);   // 20 x 256
    gemm_tc_kernel<<<ggrid, 256, GEMM_SMEM>>>(bias);

    // scan 4th -> ncu capture slot lands on it (verify the split helped)
    scan_kernel<<<BATCH, 128>>>(mask, out);

    tg_kernel<<<M_TOT / 8, 256>>>(feats, W, bias, target, mask, out);
}